// round 5
// baseline (speedup 1.0000x reference)
#include <cuda_runtime.h>
#include <cstdint>
#include <cstddef>

#define NC 10
#define DD 512
#define D4 128          // DD/4
#define SEG_BLOCKS 296
#define SEG_GROUPS (SEG_BLOCKS * 4)
#define SEG_SMEM (4 * NC * D4 * 16)   // 81920 bytes

typedef unsigned long long ull;

// Scratch (no cudaMalloc allowed)
__device__ float4 g_part4[SEG_BLOCKS * NC * D4];   // 6.06 MB partial sums
__device__ int    g_cnt_part[SEG_BLOCKS * NC];
__device__ float4 g_sums4[NC * D4];
__device__ float4 g_proto4[NC * D4];
__device__ float  g_sqp[NC];
__device__ float  g_loss;

// Packed f32x2 FMA (Blackwell): elementwise d = a*b + c on two packed floats.
static __device__ __forceinline__ ull fma2(ull a, ull b, ull c) {
    ull d;
    asm("fma.rn.f32x2 %0, %1, %2, %3;" : "=l"(d) : "l"(a), "l"(b), "l"(c));
    return d;
}
static __device__ __forceinline__ float u64_sum2(ull v) {
    float lo, hi;
    asm("mov.b64 {%0,%1}, %2;" : "=f"(lo), "=f"(hi) : "l"(v));
    return lo + hi;
}

// ---------------------------------------------------------------------------
// K1: segment sums. 512 threads = 4 independent row-groups of 128, each with
// its own 20KB smem replica -> RMW chain depth 1 per row. Partials to global.
// ---------------------------------------------------------------------------
__global__ __launch_bounds__(512) void k_segsum(const float4* __restrict__ E4,
                                                const int* __restrict__ labels,
                                                int nrows) {
    extern __shared__ float4 sm4[];            // [4][NC][D4]
    __shared__ int scnt[NC];
    const int g = threadIdx.x >> 7;            // group 0..3
    const int t = threadIdx.x & 127;           // float4 column
    float4* rep = sm4 + g * (NC * D4);

    if (threadIdx.x < NC) scnt[threadIdx.x] = 0;
#pragma unroll
    for (int c = 0; c < NC; c++) rep[c * D4 + t] = make_float4(0.f, 0.f, 0.f, 0.f);
    __syncthreads();

    const int  gid    = blockIdx.x * 4 + g;
    const long stride = (long)SEG_GROUPS * 4;
    for (long r0 = (long)gid * 4; r0 < nrows; r0 += stride) {
        if (r0 + 4 <= nrows) {
            const int4 lab4 = *(const int4*)(labels + r0);
            float4 v0 = E4[(size_t)(r0 + 0) * D4 + t];
            float4 v1 = E4[(size_t)(r0 + 1) * D4 + t];
            float4 v2 = E4[(size_t)(r0 + 2) * D4 + t];
            float4 v3 = E4[(size_t)(r0 + 3) * D4 + t];
            if (t == 0) {
                atomicAdd(&scnt[lab4.x], 1); atomicAdd(&scnt[lab4.y], 1);
                atomicAdd(&scnt[lab4.z], 1); atomicAdd(&scnt[lab4.w], 1);
            }
            float4* p;
            p = &rep[lab4.x * D4 + t];
            { float4 a = *p; a.x += v0.x; a.y += v0.y; a.z += v0.z; a.w += v0.w; *p = a; }
            p = &rep[lab4.y * D4 + t];
            { float4 a = *p; a.x += v1.x; a.y += v1.y; a.z += v1.z; a.w += v1.w; *p = a; }
            p = &rep[lab4.z * D4 + t];
            { float4 a = *p; a.x += v2.x; a.y += v2.y; a.z += v2.z; a.w += v2.w; *p = a; }
            p = &rep[lab4.w * D4 + t];
            { float4 a = *p; a.x += v3.x; a.y += v3.y; a.z += v3.z; a.w += v3.w; *p = a; }
        } else {
            for (int j = 0; j < 4 && r0 + j < nrows; j++) {
                int lj = labels[r0 + j];
                float4 v = E4[(size_t)(r0 + j) * D4 + t];
                if (t == 0) atomicAdd(&scnt[lj], 1);
                float4* p = &rep[lj * D4 + t];
                float4 a = *p; a.x += v.x; a.y += v.y; a.z += v.z; a.w += v.w; *p = a;
            }
        }
    }
    __syncthreads();

    for (int i = threadIdx.x; i < NC * D4; i += 512) {
        float4 a = sm4[i];
        float4 b = sm4[NC * D4 + i];
        float4 c = sm4[2 * NC * D4 + i];
        float4 d = sm4[3 * NC * D4 + i];
        a.x += b.x + c.x + d.x;
        a.y += b.y + c.y + d.y;
        a.z += b.z + c.z + d.z;
        a.w += b.w + c.w + d.w;
        g_part4[blockIdx.x * (NC * D4) + i] = a;
    }
    if (threadIdx.x < NC)
        g_cnt_part[blockIdx.x * NC + threadIdx.x] = scnt[threadIdx.x];
}

// ---------------------------------------------------------------------------
// K2: reduce partials -> g_sums4. grid 40 x 128: 4 threads per f4 element.
// ---------------------------------------------------------------------------
__global__ __launch_bounds__(128) void k_reduce() {
    const int i  = blockIdx.x * 32 + (threadIdx.x >> 2);   // f4 element 0..1279
    const int ps = threadIdx.x & 3;
    float4 acc = make_float4(0.f, 0.f, 0.f, 0.f);
#pragma unroll 8
    for (int p = ps; p < SEG_BLOCKS; p += 4) {
        float4 v = g_part4[p * (NC * D4) + i];
        acc.x += v.x; acc.y += v.y; acc.z += v.z; acc.w += v.w;
    }
#pragma unroll
    for (int st = 1; st <= 2; st <<= 1) {
        acc.x += __shfl_xor_sync(0xFFFFFFFFu, acc.x, st);
        acc.y += __shfl_xor_sync(0xFFFFFFFFu, acc.y, st);
        acc.z += __shfl_xor_sync(0xFFFFFFFFu, acc.z, st);
        acc.w += __shfl_xor_sync(0xFFFFFFFFu, acc.w, st);
    }
    if (ps == 0) g_sums4[i] = acc;
}

// ---------------------------------------------------------------------------
// K3: counts -> prototypes -> ||p||^2 ; also zero g_loss for this replay.
// ---------------------------------------------------------------------------
__global__ __launch_bounds__(512) void k_proto() {
    __shared__ float sinv[NC];
    const int tid = threadIdx.x, lane = tid & 31, w = tid >> 5;
    if (w < NC) {
        int s = 0;
        for (int p = lane; p < SEG_BLOCKS; p += 32) s += g_cnt_part[p * NC + w];
#pragma unroll
        for (int st = 16; st >= 1; st >>= 1) s += __shfl_xor_sync(0xFFFFFFFFu, s, st);
        if (lane == 0) sinv[w] = 1.0f / (float)s;
    }
    if (tid == 0) g_loss = 0.f;
    __syncthreads();
    const float* gs = (const float*)g_sums4;
    float*       gp = (float*)g_proto4;
#pragma unroll
    for (int c = 0; c < NC; c++) gp[c * DD + tid] = gs[c * DD + tid] * sinv[c];
    __syncthreads();
    if (w < NC) {
        const float* p = gp + w * DD;
        float acc = 0.f;
        for (int j = lane; j < DD; j += 32) acc = fmaf(p[j], p[j], acc);
#pragma unroll
        for (int st = 16; st >= 1; st >>= 1) acc += __shfl_xor_sync(0xFFFFFFFFu, acc, st);
        if (lane == 0) g_sqp[w] = acc;
    }
}

// ---------------------------------------------------------------------------
// K4 helpers. ALL intra-group shuffles use the 4-lane group mask so that
// divergence BETWEEN groups of one warp (tail block) cannot deadlock.
// ---------------------------------------------------------------------------
static __device__ __forceinline__ float row_epi(const float* dotf, float sqf,
                                                int row, int lab, bool valid,
                                                const float* __restrict__ ssqp,
                                                float* __restrict__ out,
                                                int cg, unsigned gmask) {
    float sqe = sqf;
    sqe += __shfl_xor_sync(gmask, sqe, 1);
    sqe += __shfl_xor_sync(gmask, sqe, 2);
    float l[NC];
    float m = -1e30f, lsel = 0.f;
#pragma unroll
    for (int c = 0; c < NC; c++) {
        float d = dotf[c];
        d += __shfl_xor_sync(gmask, d, 1);
        d += __shfl_xor_sync(gmask, d, 2);
        float d2 = sqe + ssqp[c] - 2.0f * d;
        float lg = -fmaxf(d2, 0.0f);
        l[c] = lg;
        m = fmaxf(m, lg);
        if (c == lab) lsel = lg;
    }
    float se = 0.f;
#pragma unroll
    for (int c = 0; c < NC; c++) se += __expf(l[c] - m);
    if (cg == 0 && valid) {
        float* o = out + 1 + (size_t)row * NC;
#pragma unroll
        for (int c = 0; c < NC; c++) o[c] = l[c];
    }
    return (cg == 0 && valid) ? (m + __logf(se) - lsel) : 0.f;
}

// Scalar path for tail rows. Row is pre-clamped; all 4 lanes of the group run.
static __device__ __forceinline__ float row_scalar(const float4* __restrict__ E4,
                                                   const float4* __restrict__ sp,
                                                   const float* __restrict__ ssqp,
                                                   int lab, float* __restrict__ out,
                                                   int row, bool valid,
                                                   int cg, unsigned gmask) {
    float dot[NC];
#pragma unroll
    for (int c = 0; c < NC; c++) dot[c] = 0.f;
    float sqf = 0.f;
    for (int t = cg; t < D4; t += 4) {
        float4 e = E4[(size_t)row * D4 + t];
        sqf += e.x * e.x + e.y * e.y + e.z * e.z + e.w * e.w;
#pragma unroll
        for (int c = 0; c < NC; c++) {
            float4 p = sp[c * D4 + t];
            dot[c] += e.x * p.x + e.y * p.y + e.z * p.z + e.w * p.w;
        }
    }
    return row_epi(dot, sqf, row, lab, valid, ssqp, out, cg, gmask);
}

// ---------------------------------------------------------------------------
// K4: logits + log-softmax + loss. 2 rows per 4-lane group, <=64 regs via
// __launch_bounds__(128, 8) -> 8 blocks/SM = 32 warps resident (occupancy is
// the binding constraint per R4 ncu: nothing saturated, occ 22.7%).
// ---------------------------------------------------------------------------
__global__ __launch_bounds__(128, 8) void k_logits(const float4* __restrict__ E4,
                                                   const int* __restrict__ labels,
                                                   float* __restrict__ out,
                                                   int nrows) {
    __shared__ float4 sp[NC * D4];   // 20 KB prototypes
    __shared__ float  ssqp[NC];
    __shared__ float  sloss;

    for (int i = threadIdx.x; i < NC * D4; i += 128) sp[i] = g_proto4[i];
    if (threadIdx.x < NC) ssqp[threadIdx.x] = g_sqp[threadIdx.x];
    if (threadIdx.x == 0) sloss = 0.f;
    __syncthreads();

    const int warp = threadIdx.x >> 5;
    const int lane = threadIdx.x & 31;
    const int cg   = lane & 3;
    const int grp  = lane >> 2;
    const unsigned gmask = 0xFu << (grp * 4);
    const int r0   = blockIdx.x * 64 + warp * 16 + grp * 2;

    float lvsum = 0.f;

    if (r0 + 2 <= nrows) {     // uniform within the 4-lane group
        const ulonglong2* __restrict__ Ep =
            (const ulonglong2*)E4 + (size_t)r0 * D4;
        const ulonglong2* __restrict__ Pp = (const ulonglong2*)sp;

        ull dot0[NC], dot1[NC];
#pragma unroll
        for (int c = 0; c < NC; c++) { dot0[c] = 0; dot1[c] = 0; }
        ull sq0 = 0, sq1 = 0;

#pragma unroll 2
        for (int k = 0; k < 32; k++) {
            const int idx = k * 4 + cg;
            ulonglong2 v0 = Ep[idx];
            ulonglong2 v1 = Ep[idx + D4];
            sq0 = fma2(v0.x, v0.x, sq0); sq0 = fma2(v0.y, v0.y, sq0);
            sq1 = fma2(v1.x, v1.x, sq1); sq1 = fma2(v1.y, v1.y, sq1);
#pragma unroll
            for (int c = 0; c < NC; c++) {
                ulonglong2 p = Pp[c * D4 + idx];
                dot0[c] = fma2(v0.x, p.x, dot0[c]); dot0[c] = fma2(v0.y, p.y, dot0[c]);
                dot1[c] = fma2(v1.x, p.x, dot1[c]); dot1[c] = fma2(v1.y, p.y, dot1[c]);
            }
        }

        const int l0 = labels[r0], l1 = labels[r0 + 1];
        float df[NC];
#pragma unroll
        for (int c = 0; c < NC; c++) df[c] = u64_sum2(dot0[c]);
        lvsum += row_epi(df, u64_sum2(sq0), r0 + 0, l0, true, ssqp, out, cg, gmask);
#pragma unroll
        for (int c = 0; c < NC; c++) df[c] = u64_sum2(dot1[c]);
        lvsum += row_epi(df, u64_sum2(sq1), r0 + 1, l1, true, ssqp, out, cg, gmask);
    } else {
        // Tail: run both rows unconditionally with clamped indices so every
        // lane of the group participates in every shuffle.
        for (int j = 0; j < 2; j++) {
            const int  row   = r0 + j;
            const bool valid = (row < nrows);
            const int  rowc  = valid ? row : (nrows > 0 ? nrows - 1 : 0);
            const int  lab   = labels[rowc];
            lvsum += row_scalar(E4, sp, ssqp, lab, out, rowc, valid, cg, gmask);
        }
    }

    // Reconverged: full-warp reduction is safe here.
#pragma unroll
    for (int st = 16; st >= 1; st >>= 1)
        lvsum += __shfl_xor_sync(0xFFFFFFFFu, lvsum, st);
    if (lane == 0) atomicAdd(&sloss, lvsum);
    __syncthreads();
    if (threadIdx.x == 0) atomicAdd(&g_loss, sloss);
}

// ---------------------------------------------------------------------------
// K5: finalize loss
// ---------------------------------------------------------------------------
__global__ void k_final(float* __restrict__ out, int nrows) {
    out[0] = g_loss * (1.0f / (float)nrows);
}

extern "C" void kernel_launch(void* const* d_in, const int* in_sizes, int n_in,
                              void* d_out, int out_size) {
    const float* E      = (const float*)d_in[0];
    const int*   labels = (const int*)d_in[1];
    float*       out    = (float*)d_out;
    const int nrows = in_sizes[1];   // 131072

    cudaFuncSetAttribute(k_segsum, cudaFuncAttributeMaxDynamicSharedMemorySize,
                         SEG_SMEM);

    k_segsum<<<SEG_BLOCKS, 512, SEG_SMEM>>>((const float4*)E, labels, nrows);
    k_reduce<<<40, 128>>>();
    k_proto<<<1, 512>>>();
    k_logits<<<(nrows + 63) / 64, 128>>>((const float4*)E, labels, out, nrows);
    k_final<<<1, 1>>>(out, nrows);
}

// round 6
// speedup vs baseline: 1.1110x; 1.1110x over previous
#include <cuda_runtime.h>
#include <cstdint>
#include <cstddef>

#define NC 10
#define DD 512
#define D4 128          // DD/4
#define SEG_BLOCKS 296
#define SEG_GROUPS (SEG_BLOCKS * 4)
#define SEG_SMEM (4 * NC * D4 * 16)   // 81920 bytes

typedef unsigned long long ull;

// Scratch (no cudaMalloc allowed)
__device__ float4 g_part4[SEG_BLOCKS * NC * D4];   // 6.06 MB partial sums
__device__ int    g_cnt_part[SEG_BLOCKS * NC];
__device__ float4 g_sums4[NC * D4];
__device__ float4 g_proto4[NC * D4];
__device__ float  g_sqp[NC];
__device__ float  g_loss;

// Packed f32x2 FMA (Blackwell): elementwise d = a*b + c on two packed floats.
static __device__ __forceinline__ ull fma2(ull a, ull b, ull c) {
    ull d;
    asm("fma.rn.f32x2 %0, %1, %2, %3;" : "=l"(d) : "l"(a), "l"(b), "l"(c));
    return d;
}
static __device__ __forceinline__ float u64_sum2(ull v) {
    float lo, hi;
    asm("mov.b64 {%0,%1}, %2;" : "=f"(lo), "=f"(hi) : "l"(v));
    return lo + hi;
}

// ---------------------------------------------------------------------------
// K1: segment sums. 512 threads = 4 independent row-groups of 128, each with
// its own 20KB smem replica -> RMW chain depth 1 per row. Partials to global.
// ---------------------------------------------------------------------------
__global__ __launch_bounds__(512) void k_segsum(const float4* __restrict__ E4,
                                                const int* __restrict__ labels,
                                                int nrows) {
    extern __shared__ float4 sm4[];            // [4][NC][D4]
    __shared__ int scnt[NC];
    const int g = threadIdx.x >> 7;            // group 0..3
    const int t = threadIdx.x & 127;           // float4 column
    float4* rep = sm4 + g * (NC * D4);

    if (threadIdx.x < NC) scnt[threadIdx.x] = 0;
#pragma unroll
    for (int c = 0; c < NC; c++) rep[c * D4 + t] = make_float4(0.f, 0.f, 0.f, 0.f);
    __syncthreads();

    const int  gid    = blockIdx.x * 4 + g;
    const long stride = (long)SEG_GROUPS * 4;
    for (long r0 = (long)gid * 4; r0 < nrows; r0 += stride) {
        if (r0 + 4 <= nrows) {
            const int4 lab4 = *(const int4*)(labels + r0);
            float4 v0 = E4[(size_t)(r0 + 0) * D4 + t];
            float4 v1 = E4[(size_t)(r0 + 1) * D4 + t];
            float4 v2 = E4[(size_t)(r0 + 2) * D4 + t];
            float4 v3 = E4[(size_t)(r0 + 3) * D4 + t];
            if (t == 0) {
                atomicAdd(&scnt[lab4.x], 1); atomicAdd(&scnt[lab4.y], 1);
                atomicAdd(&scnt[lab4.z], 1); atomicAdd(&scnt[lab4.w], 1);
            }
            float4* p;
            p = &rep[lab4.x * D4 + t];
            { float4 a = *p; a.x += v0.x; a.y += v0.y; a.z += v0.z; a.w += v0.w; *p = a; }
            p = &rep[lab4.y * D4 + t];
            { float4 a = *p; a.x += v1.x; a.y += v1.y; a.z += v1.z; a.w += v1.w; *p = a; }
            p = &rep[lab4.z * D4 + t];
            { float4 a = *p; a.x += v2.x; a.y += v2.y; a.z += v2.z; a.w += v2.w; *p = a; }
            p = &rep[lab4.w * D4 + t];
            { float4 a = *p; a.x += v3.x; a.y += v3.y; a.z += v3.z; a.w += v3.w; *p = a; }
        } else {
            for (int j = 0; j < 4 && r0 + j < nrows; j++) {
                int lj = labels[r0 + j];
                float4 v = E4[(size_t)(r0 + j) * D4 + t];
                if (t == 0) atomicAdd(&scnt[lj], 1);
                float4* p = &rep[lj * D4 + t];
                float4 a = *p; a.x += v.x; a.y += v.y; a.z += v.z; a.w += v.w; *p = a;
            }
        }
    }
    __syncthreads();

    for (int i = threadIdx.x; i < NC * D4; i += 512) {
        float4 a = sm4[i];
        float4 b = sm4[NC * D4 + i];
        float4 c = sm4[2 * NC * D4 + i];
        float4 d = sm4[3 * NC * D4 + i];
        a.x += b.x + c.x + d.x;
        a.y += b.y + c.y + d.y;
        a.z += b.z + c.z + d.z;
        a.w += b.w + c.w + d.w;
        g_part4[blockIdx.x * (NC * D4) + i] = a;
    }
    if (threadIdx.x < NC)
        g_cnt_part[blockIdx.x * NC + threadIdx.x] = scnt[threadIdx.x];
}

// ---------------------------------------------------------------------------
// K2: reduce partials -> g_sums4. grid 40 x 128: 4 threads per f4 element.
// ---------------------------------------------------------------------------
__global__ __launch_bounds__(128) void k_reduce() {
    const int i  = blockIdx.x * 32 + (threadIdx.x >> 2);   // f4 element 0..1279
    const int ps = threadIdx.x & 3;
    float4 acc = make_float4(0.f, 0.f, 0.f, 0.f);
#pragma unroll 8
    for (int p = ps; p < SEG_BLOCKS; p += 4) {
        float4 v = g_part4[p * (NC * D4) + i];
        acc.x += v.x; acc.y += v.y; acc.z += v.z; acc.w += v.w;
    }
#pragma unroll
    for (int st = 1; st <= 2; st <<= 1) {
        acc.x += __shfl_xor_sync(0xFFFFFFFFu, acc.x, st);
        acc.y += __shfl_xor_sync(0xFFFFFFFFu, acc.y, st);
        acc.z += __shfl_xor_sync(0xFFFFFFFFu, acc.z, st);
        acc.w += __shfl_xor_sync(0xFFFFFFFFu, acc.w, st);
    }
    if (ps == 0) g_sums4[i] = acc;
}

// ---------------------------------------------------------------------------
// K3: counts -> prototypes -> ||p||^2 ; also zero g_loss for this replay.
// ---------------------------------------------------------------------------
__global__ __launch_bounds__(512) void k_proto() {
    __shared__ float sinv[NC];
    const int tid = threadIdx.x, lane = tid & 31, w = tid >> 5;
    if (w < NC) {
        int s = 0;
        for (int p = lane; p < SEG_BLOCKS; p += 32) s += g_cnt_part[p * NC + w];
#pragma unroll
        for (int st = 16; st >= 1; st >>= 1) s += __shfl_xor_sync(0xFFFFFFFFu, s, st);
        if (lane == 0) sinv[w] = 1.0f / (float)s;
    }
    if (tid == 0) g_loss = 0.f;
    __syncthreads();
    const float* gs = (const float*)g_sums4;
    float*       gp = (float*)g_proto4;
#pragma unroll
    for (int c = 0; c < NC; c++) gp[c * DD + tid] = gs[c * DD + tid] * sinv[c];
    __syncthreads();
    if (w < NC) {
        const float* p = gp + w * DD;
        float acc = 0.f;
        for (int j = lane; j < DD; j += 32) acc = fmaf(p[j], p[j], acc);
#pragma unroll
        for (int st = 16; st >= 1; st >>= 1) acc += __shfl_xor_sync(0xFFFFFFFFu, acc, st);
        if (lane == 0) g_sqp[w] = acc;
    }
}

// ---------------------------------------------------------------------------
// K4: logits + log-softmax + loss.
// Lane layout per warp: lane = g*8 + ch*4 + dimq.
//   g    (0..3): 8-lane group, owns 4 consecutive rows
//   ch   (0..1): class half (classes ch*5 .. ch*5+4)
//   dimq (0..3): dim quarter (f4 chunks idx = k*4+dimq)
// Each thread: 4 rows x 5 classes of packed-f32x2 accumulators (40 regs).
// Single always-clamped code path: loads never OOB, stores gated by `valid`,
// all group shuffles use the 8-lane gmask (no divergence hazards).
// ---------------------------------------------------------------------------
__global__ __launch_bounds__(128, 5) void k_logits(const float4* __restrict__ E4,
                                                   const int* __restrict__ labels,
                                                   float* __restrict__ out,
                                                   int nrows) {
    __shared__ float4 sp[NC * D4];   // 20 KB prototypes
    __shared__ float  ssqp[NC];
    __shared__ float  sloss;

    for (int i = threadIdx.x; i < NC * D4; i += 128) sp[i] = g_proto4[i];
    if (threadIdx.x < NC) ssqp[threadIdx.x] = g_sqp[threadIdx.x];
    if (threadIdx.x == 0) sloss = 0.f;
    __syncthreads();

    const int warp = threadIdx.x >> 5;
    const int lane = threadIdx.x & 31;
    const int dimq = lane & 3;
    const int ch   = (lane >> 2) & 1;
    const int g    = lane >> 3;
    const unsigned gmask = 0xFFu << (g * 8);
    const int r0   = blockIdx.x * 64 + warp * 16 + g * 4;

    // Clamped row indices: loads always in-bounds, stores gated by valid.
    int  rowc[4];
    bool valid[4];
#pragma unroll
    for (int j = 0; j < 4; j++) {
        int r = r0 + j;
        valid[j] = (r < nrows);
        rowc[j]  = valid[j] ? r : (nrows - 1);
    }

    const ulonglong2* __restrict__ Pp = (const ulonglong2*)sp;
    const ulonglong2* __restrict__ Ep0 = (const ulonglong2*)E4 + (size_t)rowc[0] * D4;
    const ulonglong2* __restrict__ Ep1 = (const ulonglong2*)E4 + (size_t)rowc[1] * D4;
    const ulonglong2* __restrict__ Ep2 = (const ulonglong2*)E4 + (size_t)rowc[2] * D4;
    const ulonglong2* __restrict__ Ep3 = (const ulonglong2*)E4 + (size_t)rowc[3] * D4;
    const ulonglong2* __restrict__ Pc  = Pp + (size_t)(ch * 5) * D4;

    ull dot[4][5];
#pragma unroll
    for (int j = 0; j < 4; j++)
#pragma unroll
        for (int c = 0; c < 5; c++) dot[j][c] = 0ull;
    ull sq[4] = {0ull, 0ull, 0ull, 0ull};

#pragma unroll 2
    for (int k = 0; k < 32; k++) {
        const int idx = k * 4 + dimq;
        ulonglong2 v0 = Ep0[idx];
        ulonglong2 v1 = Ep1[idx];
        ulonglong2 v2 = Ep2[idx];
        ulonglong2 v3 = Ep3[idx];
        sq[0] = fma2(v0.x, v0.x, sq[0]); sq[0] = fma2(v0.y, v0.y, sq[0]);
        sq[1] = fma2(v1.x, v1.x, sq[1]); sq[1] = fma2(v1.y, v1.y, sq[1]);
        sq[2] = fma2(v2.x, v2.x, sq[2]); sq[2] = fma2(v2.y, v2.y, sq[2]);
        sq[3] = fma2(v3.x, v3.x, sq[3]); sq[3] = fma2(v3.y, v3.y, sq[3]);
#pragma unroll
        for (int c = 0; c < 5; c++) {
            ulonglong2 p = Pc[c * D4 + idx];
            dot[0][c] = fma2(v0.x, p.x, dot[0][c]); dot[0][c] = fma2(v0.y, p.y, dot[0][c]);
            dot[1][c] = fma2(v1.x, p.x, dot[1][c]); dot[1][c] = fma2(v1.y, p.y, dot[1][c]);
            dot[2][c] = fma2(v2.x, p.x, dot[2][c]); dot[2][c] = fma2(v2.y, p.y, dot[2][c]);
            dot[3][c] = fma2(v3.x, p.x, dot[3][c]); dot[3][c] = fma2(v3.y, p.y, dot[3][c]);
        }
    }

    float lvsum = 0.f;
#pragma unroll
    for (int j = 0; j < 4; j++) {
        // Reduce over the 4 dim-quarter lanes (xor 1, 2 stay within class-half).
        float sqe = u64_sum2(sq[j]);
        sqe += __shfl_xor_sync(gmask, sqe, 1);
        sqe += __shfl_xor_sync(gmask, sqe, 2);

        float l[5];
        float m5 = -1e30f;
#pragma unroll
        for (int c = 0; c < 5; c++) {
            float d = u64_sum2(dot[j][c]);
            d += __shfl_xor_sync(gmask, d, 1);
            d += __shfl_xor_sync(gmask, d, 2);
            float d2 = sqe + ssqp[ch * 5 + c] - 2.0f * d;
            float lg = -fmaxf(d2, 0.0f);
            l[c] = lg;
            m5 = fmaxf(m5, lg);
        }
        // Combine the two class halves (xor 4 swaps ch within the group).
        float m = fmaxf(m5, __shfl_xor_sync(gmask, m5, 4));
        float se5 = 0.f;
#pragma unroll
        for (int c = 0; c < 5; c++) se5 += __expf(l[c] - m);
        float se = se5 + __shfl_xor_sync(gmask, se5, 4);

        const int lab = labels[rowc[j]];
        float lsel5 = 0.f;
#pragma unroll
        for (int c = 0; c < 5; c++)
            if (ch * 5 + c == lab) lsel5 = l[c];
        float lsel = lsel5 + __shfl_xor_sync(gmask, lsel5, 4);

        if (dimq == 0 && valid[j]) {
            float* o = out + 1 + (size_t)rowc[j] * NC + ch * 5;
#pragma unroll
            for (int c = 0; c < 5; c++) o[c] = l[c];
        }
        if (dimq == 0 && ch == 0 && valid[j])
            lvsum += m + __logf(se) - lsel;
    }

    // Reconverged: full-warp reduction is safe here.
#pragma unroll
    for (int st = 16; st >= 1; st >>= 1)
        lvsum += __shfl_xor_sync(0xFFFFFFFFu, lvsum, st);
    if (lane == 0) atomicAdd(&sloss, lvsum);
    __syncthreads();
    if (threadIdx.x == 0) atomicAdd(&g_loss, sloss);
}

// ---------------------------------------------------------------------------
// K5: finalize loss
// ---------------------------------------------------------------------------
__global__ void k_final(float* __restrict__ out, int nrows) {
    out[0] = g_loss * (1.0f / (float)nrows);
}

extern "C" void kernel_launch(void* const* d_in, const int* in_sizes, int n_in,
                              void* d_out, int out_size) {
    const float* E      = (const float*)d_in[0];
    const int*   labels = (const int*)d_in[1];
    float*       out    = (float*)d_out;
    const int nrows = in_sizes[1];   // 131072

    cudaFuncSetAttribute(k_segsum, cudaFuncAttributeMaxDynamicSharedMemorySize,
                         SEG_SMEM);

    k_segsum<<<SEG_BLOCKS, 512, SEG_SMEM>>>((const float4*)E, labels, nrows);
    k_reduce<<<40, 128>>>();
    k_proto<<<1, 512>>>();
    k_logits<<<(nrows + 63) / 64, 128>>>((const float4*)E, labels, out, nrows);
    k_final<<<1, 1>>>(out, nrows);
}

// round 7
// speedup vs baseline: 1.1288x; 1.0160x over previous
#include <cuda_runtime.h>
#include <cstdint>
#include <cstddef>

#define NC 10
#define DD 512
#define D4 128          // DD/4
#define SEG_BLOCKS 296
#define SEG_GROUPS (SEG_BLOCKS * 4)
#define SEG_SMEM (4 * NC * D4 * 16)   // 81920 bytes

typedef unsigned long long ull;

// Scratch (no cudaMalloc allowed)
__device__ float4 g_part4[SEG_BLOCKS * NC * D4];   // 6.06 MB partial sums
__device__ int    g_cnt_part[SEG_BLOCKS * NC];
__device__ float4 g_sums4[NC * D4];
__device__ float4 g_proto4[NC * D4];
__device__ float  g_sqp[NC];
__device__ float  g_loss;

// Packed f32x2 FMA (Blackwell): elementwise d = a*b + c on two packed floats.
static __device__ __forceinline__ ull fma2(ull a, ull b, ull c) {
    ull d;
    asm("fma.rn.f32x2 %0, %1, %2, %3;" : "=l"(d) : "l"(a), "l"(b), "l"(c));
    return d;
}
static __device__ __forceinline__ float u64_sum2(ull v) {
    float lo, hi;
    asm("mov.b64 {%0,%1}, %2;" : "=f"(lo), "=f"(hi) : "l"(v));
    return lo + hi;
}

// ---------------------------------------------------------------------------
// K1: segment sums. 512 threads = 4 independent row-groups of 128, each with
// its own 20KB smem replica -> RMW chain depth 1 per row. Partials to global.
// ---------------------------------------------------------------------------
__global__ __launch_bounds__(512) void k_segsum(const float4* __restrict__ E4,
                                                const int* __restrict__ labels,
                                                int nrows) {
    extern __shared__ float4 sm4[];            // [4][NC][D4]
    __shared__ int scnt[NC];
    const int g = threadIdx.x >> 7;            // group 0..3
    const int t = threadIdx.x & 127;           // float4 column
    float4* rep = sm4 + g * (NC * D4);

    if (threadIdx.x < NC) scnt[threadIdx.x] = 0;
#pragma unroll
    for (int c = 0; c < NC; c++) rep[c * D4 + t] = make_float4(0.f, 0.f, 0.f, 0.f);
    __syncthreads();

    const int  gid    = blockIdx.x * 4 + g;
    const long stride = (long)SEG_GROUPS * 4;
    for (long r0 = (long)gid * 4; r0 < nrows; r0 += stride) {
        if (r0 + 4 <= nrows) {
            const int4 lab4 = *(const int4*)(labels + r0);
            float4 v0 = E4[(size_t)(r0 + 0) * D4 + t];
            float4 v1 = E4[(size_t)(r0 + 1) * D4 + t];
            float4 v2 = E4[(size_t)(r0 + 2) * D4 + t];
            float4 v3 = E4[(size_t)(r0 + 3) * D4 + t];
            if (t == 0) {
                atomicAdd(&scnt[lab4.x], 1); atomicAdd(&scnt[lab4.y], 1);
                atomicAdd(&scnt[lab4.z], 1); atomicAdd(&scnt[lab4.w], 1);
            }
            float4* p;
            p = &rep[lab4.x * D4 + t];
            { float4 a = *p; a.x += v0.x; a.y += v0.y; a.z += v0.z; a.w += v0.w; *p = a; }
            p = &rep[lab4.y * D4 + t];
            { float4 a = *p; a.x += v1.x; a.y += v1.y; a.z += v1.z; a.w += v1.w; *p = a; }
            p = &rep[lab4.z * D4 + t];
            { float4 a = *p; a.x += v2.x; a.y += v2.y; a.z += v2.z; a.w += v2.w; *p = a; }
            p = &rep[lab4.w * D4 + t];
            { float4 a = *p; a.x += v3.x; a.y += v3.y; a.z += v3.z; a.w += v3.w; *p = a; }
        } else {
            for (int j = 0; j < 4 && r0 + j < nrows; j++) {
                int lj = labels[r0 + j];
                float4 v = E4[(size_t)(r0 + j) * D4 + t];
                if (t == 0) atomicAdd(&scnt[lj], 1);
                float4* p = &rep[lj * D4 + t];
                float4 a = *p; a.x += v.x; a.y += v.y; a.z += v.z; a.w += v.w; *p = a;
            }
        }
    }
    __syncthreads();

    for (int i = threadIdx.x; i < NC * D4; i += 512) {
        float4 a = sm4[i];
        float4 b = sm4[NC * D4 + i];
        float4 c = sm4[2 * NC * D4 + i];
        float4 d = sm4[3 * NC * D4 + i];
        a.x += b.x + c.x + d.x;
        a.y += b.y + c.y + d.y;
        a.z += b.z + c.z + d.z;
        a.w += b.w + c.w + d.w;
        g_part4[blockIdx.x * (NC * D4) + i] = a;
    }
    if (threadIdx.x < NC)
        g_cnt_part[blockIdx.x * NC + threadIdx.x] = scnt[threadIdx.x];
}

// ---------------------------------------------------------------------------
// K2: reduce partials -> g_sums4. grid 40 x 128: 4 threads per f4 element.
// ---------------------------------------------------------------------------
__global__ __launch_bounds__(128) void k_reduce() {
    const int i  = blockIdx.x * 32 + (threadIdx.x >> 2);   // f4 element 0..1279
    const int ps = threadIdx.x & 3;
    float4 acc = make_float4(0.f, 0.f, 0.f, 0.f);
#pragma unroll 8
    for (int p = ps; p < SEG_BLOCKS; p += 4) {
        float4 v = g_part4[p * (NC * D4) + i];
        acc.x += v.x; acc.y += v.y; acc.z += v.z; acc.w += v.w;
    }
#pragma unroll
    for (int st = 1; st <= 2; st <<= 1) {
        acc.x += __shfl_xor_sync(0xFFFFFFFFu, acc.x, st);
        acc.y += __shfl_xor_sync(0xFFFFFFFFu, acc.y, st);
        acc.z += __shfl_xor_sync(0xFFFFFFFFu, acc.z, st);
        acc.w += __shfl_xor_sync(0xFFFFFFFFu, acc.w, st);
    }
    if (ps == 0) g_sums4[i] = acc;
}

// ---------------------------------------------------------------------------
// K3: counts -> prototypes -> ||p||^2 ; also zero g_loss for this replay.
// ---------------------------------------------------------------------------
__global__ __launch_bounds__(512) void k_proto() {
    __shared__ float sinv[NC];
    const int tid = threadIdx.x, lane = tid & 31, w = tid >> 5;
    if (w < NC) {
        int s = 0;
        for (int p = lane; p < SEG_BLOCKS; p += 32) s += g_cnt_part[p * NC + w];
#pragma unroll
        for (int st = 16; st >= 1; st >>= 1) s += __shfl_xor_sync(0xFFFFFFFFu, s, st);
        if (lane == 0) sinv[w] = 1.0f / (float)s;
    }
    if (tid == 0) g_loss = 0.f;
    __syncthreads();
    const float* gs = (const float*)g_sums4;
    float*       gp = (float*)g_proto4;
#pragma unroll
    for (int c = 0; c < NC; c++) gp[c * DD + tid] = gs[c * DD + tid] * sinv[c];
    __syncthreads();
    if (w < NC) {
        const float* p = gp + w * DD;
        float acc = 0.f;
        for (int j = lane; j < DD; j += 32) acc = fmaf(p[j], p[j], acc);
#pragma unroll
        for (int st = 16; st >= 1; st >>= 1) acc += __shfl_xor_sync(0xFFFFFFFFu, acc, st);
        if (lane == 0) g_sqp[w] = acc;
    }
}

// ---------------------------------------------------------------------------
// K4: logits + log-softmax + loss.
// Lane layout per warp: lane = g*8 + ch*4 + dimq.
//   g    (0..3): 8-lane group, owns 4 consecutive rows
//   ch   (0..1): class half (classes ch*5 .. ch*5+4)
//   dimq (0..3): dim quarter
// Two k-chunks per iteration -> 8 independent LDG.128 batched at loop top
// (Little's law: 16 warps x 8 x 128B = 16KB/SM in flight -> ~5TB/s DRAM).
// Single always-clamped code path; 8-lane gmask shuffles only.
// ---------------------------------------------------------------------------
__global__ __launch_bounds__(128, 4) void k_logits(const float4* __restrict__ E4,
                                                   const int* __restrict__ labels,
                                                   float* __restrict__ out,
                                                   int nrows) {
    __shared__ float4 sp[NC * D4];   // 20 KB prototypes
    __shared__ float  ssqp[NC];
    __shared__ float  sloss;

    for (int i = threadIdx.x; i < NC * D4; i += 128) sp[i] = g_proto4[i];
    if (threadIdx.x < NC) ssqp[threadIdx.x] = g_sqp[threadIdx.x];
    if (threadIdx.x == 0) sloss = 0.f;
    __syncthreads();

    const int warp = threadIdx.x >> 5;
    const int lane = threadIdx.x & 31;
    const int dimq = lane & 3;
    const int ch   = (lane >> 2) & 1;
    const int g    = lane >> 3;
    const unsigned gmask = 0xFFu << (g * 8);
    const int r0   = blockIdx.x * 64 + warp * 16 + g * 4;

    // Clamped row indices: loads always in-bounds, stores gated by valid.
    int  rowc[4];
    bool valid[4];
#pragma unroll
    for (int j = 0; j < 4; j++) {
        int r = r0 + j;
        valid[j] = (r < nrows);
        rowc[j]  = valid[j] ? r : (nrows - 1);
    }

    const ulonglong2* __restrict__ Pp  = (const ulonglong2*)sp;
    const ulonglong2* __restrict__ Ep0 = (const ulonglong2*)E4 + (size_t)rowc[0] * D4;
    const ulonglong2* __restrict__ Ep1 = (const ulonglong2*)E4 + (size_t)rowc[1] * D4;
    const ulonglong2* __restrict__ Ep2 = (const ulonglong2*)E4 + (size_t)rowc[2] * D4;
    const ulonglong2* __restrict__ Ep3 = (const ulonglong2*)E4 + (size_t)rowc[3] * D4;
    const ulonglong2* __restrict__ Pc  = Pp + (size_t)(ch * 5) * D4;

    ull dot[4][5];
#pragma unroll
    for (int j = 0; j < 4; j++)
#pragma unroll
        for (int c = 0; c < 5; c++) dot[j][c] = 0ull;
    ull sq[4] = {0ull, 0ull, 0ull, 0ull};

#pragma unroll 2
    for (int k = 0; k < 16; k++) {
        const int ia = k * 8 + dimq;      // chunk A
        const int ib = ia + 4;            // chunk B
        // 8 independent LDG.128 batched up front
        ulonglong2 a0 = Ep0[ia], a1 = Ep1[ia], a2 = Ep2[ia], a3 = Ep3[ia];
        ulonglong2 b0 = Ep0[ib], b1 = Ep1[ib], b2 = Ep2[ib], b3 = Ep3[ib];

        sq[0] = fma2(a0.x, a0.x, sq[0]); sq[0] = fma2(a0.y, a0.y, sq[0]);
        sq[1] = fma2(a1.x, a1.x, sq[1]); sq[1] = fma2(a1.y, a1.y, sq[1]);
        sq[2] = fma2(a2.x, a2.x, sq[2]); sq[2] = fma2(a2.y, a2.y, sq[2]);
        sq[3] = fma2(a3.x, a3.x, sq[3]); sq[3] = fma2(a3.y, a3.y, sq[3]);
        sq[0] = fma2(b0.x, b0.x, sq[0]); sq[0] = fma2(b0.y, b0.y, sq[0]);
        sq[1] = fma2(b1.x, b1.x, sq[1]); sq[1] = fma2(b1.y, b1.y, sq[1]);
        sq[2] = fma2(b2.x, b2.x, sq[2]); sq[2] = fma2(b2.y, b2.y, sq[2]);
        sq[3] = fma2(b3.x, b3.x, sq[3]); sq[3] = fma2(b3.y, b3.y, sq[3]);
#pragma unroll
        for (int c = 0; c < 5; c++) {
            ulonglong2 pa = Pc[c * D4 + ia];
            ulonglong2 pb = Pc[c * D4 + ib];
            dot[0][c] = fma2(a0.x, pa.x, dot[0][c]); dot[0][c] = fma2(a0.y, pa.y, dot[0][c]);
            dot[1][c] = fma2(a1.x, pa.x, dot[1][c]); dot[1][c] = fma2(a1.y, pa.y, dot[1][c]);
            dot[2][c] = fma2(a2.x, pa.x, dot[2][c]); dot[2][c] = fma2(a2.y, pa.y, dot[2][c]);
            dot[3][c] = fma2(a3.x, pa.x, dot[3][c]); dot[3][c] = fma2(a3.y, pa.y, dot[3][c]);
            dot[0][c] = fma2(b0.x, pb.x, dot[0][c]); dot[0][c] = fma2(b0.y, pb.y, dot[0][c]);
            dot[1][c] = fma2(b1.x, pb.x, dot[1][c]); dot[1][c] = fma2(b1.y, pb.y, dot[1][c]);
            dot[2][c] = fma2(b2.x, pb.x, dot[2][c]); dot[2][c] = fma2(b2.y, pb.y, dot[2][c]);
            dot[3][c] = fma2(b3.x, pb.x, dot[3][c]); dot[3][c] = fma2(b3.y, pb.y, dot[3][c]);
        }
    }

    float lvsum = 0.f;
#pragma unroll
    for (int j = 0; j < 4; j++) {
        // Reduce over the 4 dim-quarter lanes (xor 1, 2 stay within class-half).
        float sqe = u64_sum2(sq[j]);
        sqe += __shfl_xor_sync(gmask, sqe, 1);
        sqe += __shfl_xor_sync(gmask, sqe, 2);

        float l[5];
        float m5 = -1e30f;
#pragma unroll
        for (int c = 0; c < 5; c++) {
            float d = u64_sum2(dot[j][c]);
            d += __shfl_xor_sync(gmask, d, 1);
            d += __shfl_xor_sync(gmask, d, 2);
            float d2 = sqe + ssqp[ch * 5 + c] - 2.0f * d;
            float lg = -fmaxf(d2, 0.0f);
            l[c] = lg;
            m5 = fmaxf(m5, lg);
        }
        // Combine the two class halves (xor 4 swaps ch within the group).
        float m = fmaxf(m5, __shfl_xor_sync(gmask, m5, 4));
        float se5 = 0.f;
#pragma unroll
        for (int c = 0; c < 5; c++) se5 += __expf(l[c] - m);
        float se = se5 + __shfl_xor_sync(gmask, se5, 4);

        const int lab = labels[rowc[j]];
        float lsel5 = 0.f;
#pragma unroll
        for (int c = 0; c < 5; c++)
            if (ch * 5 + c == lab) lsel5 = l[c];
        float lsel = lsel5 + __shfl_xor_sync(gmask, lsel5, 4);

        if (dimq == 0 && valid[j]) {
            float* o = out + 1 + (size_t)rowc[j] * NC + ch * 5;
#pragma unroll
            for (int c = 0; c < 5; c++) o[c] = l[c];
        }
        if (dimq == 0 && ch == 0 && valid[j])
            lvsum += m + __logf(se) - lsel;
    }

    // Reconverged: full-warp reduction is safe here.
#pragma unroll
    for (int st = 16; st >= 1; st >>= 1)
        lvsum += __shfl_xor_sync(0xFFFFFFFFu, lvsum, st);
    if (lane == 0) atomicAdd(&sloss, lvsum);
    __syncthreads();
    if (threadIdx.x == 0) atomicAdd(&g_loss, sloss);
}

// ---------------------------------------------------------------------------
// K5: finalize loss
// ---------------------------------------------------------------------------
__global__ void k_final(float* __restrict__ out, int nrows) {
    out[0] = g_loss * (1.0f / (float)nrows);
}

extern "C" void kernel_launch(void* const* d_in, const int* in_sizes, int n_in,
                              void* d_out, int out_size) {
    const float* E      = (const float*)d_in[0];
    const int*   labels = (const int*)d_in[1];
    float*       out    = (float*)d_out;
    const int nrows = in_sizes[1];   // 131072

    cudaFuncSetAttribute(k_segsum, cudaFuncAttributeMaxDynamicSharedMemorySize,
                         SEG_SMEM);

    k_segsum<<<SEG_BLOCKS, 512, SEG_SMEM>>>((const float4*)E, labels, nrows);
    k_reduce<<<40, 128>>>();
    k_proto<<<1, 512>>>();
    k_logits<<<(nrows + 63) / 64, 128>>>((const float4*)E, labels, out, nrows);
    k_final<<<1, 1>>>(out, nrows);
}